// round 9
// baseline (speedup 1.0000x reference)
#include <cuda_runtime.h>

// bicon_loss fused single kernel, R9:
//  - 4 px/thread (float4), ALL c_map loads hoisted into one branch-free batch
//    (clamped row offsets + multiplicative validity masks) -> ~29 LDGs in
//    flight per thread before any dependent compute.
//  - con loads front-batched (__ldcs) -> one 32-bit mask (R8 win, kept)
//  - HW tanh sigmoid, log-factored BCE (lower-clamp only per term),
//    signed min/max accumulator, threadfence reduction.

#define BB 16
#define HH 352
#define WW 352
#define HW (HH * WW)
#define WV (WW / 4)              // 88 vec-cols
#define NTH (BB * HH * WV)       // 495616 threads
#define TPB 256
#define NBLK (NTH / TPB)         // 1936 exactly

__device__ float        g_part[NBLK];
__device__ unsigned int g_cnt = 0;

__device__ __forceinline__ float sigf(float x) {
    float t;
    asm("tanh.approx.f32 %0, %1;" : "=f"(t) : "f"(x * 0.5f));
    return fmaf(0.5f, t, 0.5f);
}
__device__ __forceinline__ float clipf(float v) {
    return fminf(fmaxf(v, 1e-7f), 1.0f - 1e-7f);
}

__global__ void __launch_bounds__(TPB, 3)
bicon_loss_kernel(const float* __restrict__ c_map,
                  const float* __restrict__ target,
                  const int*   __restrict__ con,
                  float*       __restrict__ out)
{
    const int tid  = blockIdx.x * TPB + threadIdx.x;   // grid covers NTH exactly
    const int wv   = tid % WV;
    const int rest = tid / WV;
    const int h    = rest % HH;
    const int b    = rest / HH;
    const int w0   = wv * 4;

    const size_t roff = (size_t)h * WW + w0;
    const float* cmb = c_map + (size_t)b * 8 * HW + roff;
    const int*   cnb = con   + (size_t)b * 8 * HW + roff;

    // validity: clamped offsets keep every load in-bounds; masks zero the result
    const bool wl = (w0 > 0), wr = (wv < WV - 1);
    const int   hs_u = (h > 0)      ? -WW : 0;
    const int   hs_d = (h < HH - 1) ?  WW : 0;
    const float mu   = (h > 0)      ? 1.0f : 0.0f;
    const float mdn  = (h < HH - 1) ? 1.0f : 0.0f;
    const int   ol   = wl ? -1 : 0;
    const int   orr  = wr ?  4 : 3;
    const float mlf  = wl ? 1.0f : 0.0f;
    const float mrf  = wr ? 1.0f : 0.0f;

    // ================= Phase A: all independent global loads =================
    float4 xs[8];
    #pragma unroll
    for (int c = 0; c < 8; c++)
        xs[c] = *(const float4*)(cmb + c * HW);

    const float4 xu7 = *(const float4*)(cmb + 7 * HW + hs_u);
    const float4 xu6 = *(const float4*)(cmb + 6 * HW + hs_u);
    const float4 xu5 = *(const float4*)(cmb + 5 * HW + hs_u);
    const float4 xd0 = *(const float4*)(cmb + 0 * HW + hs_d);
    const float4 xd1 = *(const float4*)(cmb + 1 * HW + hs_d);
    const float4 xd2 = *(const float4*)(cmb + 2 * HW + hs_d);

    const float eu7 = (cmb + 7 * HW + hs_u)[ol];    // pair0 si edge (left)
    const float eu5 = (cmb + 5 * HW + hs_u)[orr];   // pair2 si edge (right)
    const float ed0 = (cmb + 0 * HW + hs_d)[orr];   // pair0 sj edge (right)
    const float ed2 = (cmb + 2 * HW + hs_d)[ol];    // pair2 sj edge (left)
    const float e4l = cmb[4 * HW + ol];             // pair3 si edge (left)
    const float e3r = cmb[3 * HW + orr];            // pair3 sj edge (right)

    unsigned m = 0u;        // bit (c + 8q) = con[c] at pixel q
    #pragma unroll
    for (int c = 0; c < 8; c++) {
        const int4 t = __ldcs((const int4*)(cnb + c * HW));
        m |= ((unsigned)(t.x != 0) << (c + 0))
           | ((unsigned)(t.y != 0) << (c + 8))
           | ((unsigned)(t.z != 0) << (c + 16))
           | ((unsigned)(t.w != 0) << (c + 24));
    }
    const float4 tg4 = __ldcs((const float4*)(target + (size_t)b * HW + roff));

    // ================= Phase B: sigmoids =================
    float p[8][4];
    #pragma unroll
    for (int c = 0; c < 8; c++) {
        p[c][0] = sigf(xs[c].x); p[c][1] = sigf(xs[c].y);
        p[c][2] = sigf(xs[c].z); p[c][3] = sigf(xs[c].w);
    }

    // edge & con-BCE products (independent of votes)
    bool  edge[4];
    float sgn[4], dacc[4];
    float pc0[4] = {1.f,1.f,1.f,1.f}, pc1[4] = {1.f,1.f,1.f,1.f};
    #pragma unroll
    for (int q = 0; q < 4; q++) {
        const int sc = __popc((m >> (8 * q)) & 0xffu);
        edge[q] = (sc > 0) && (sc < 8);
        sgn[q]  = edge[q] ? -1.0f : 1.0f;
        dacc[q] = -1e30f;
        #pragma unroll
        for (int c = 0; c < 4; c++) {
            const int cj = 7 - c;
            const bool bi = (m >> (c  + 8 * q)) & 1u;
            const bool bj = (m >> (cj + 8 * q)) & 1u;
            pc0[q] *= fmaxf(bi ? p[c][q]  : 1.0f - p[c][q],  1e-7f);
            pc1[q] *= fmaxf(bj ? p[cj][q] : 1.0f - p[cj][q], 1e-7f);
        }
    }

    // neighbor sigmoids, per pair, already shifted per pixel q (masks folded in)
    // pair K: vote_K = p[K]*sKi ; vote_{7-K} = p[7-K]*sKj
    const float s0i[4] = { sigf(eu7)*(mu*mlf),  sigf(xu7.x)*mu, sigf(xu7.y)*mu, sigf(xu7.z)*mu };
    const float s0j[4] = { sigf(xd0.y)*mdn, sigf(xd0.z)*mdn, sigf(xd0.w)*mdn, sigf(ed0)*(mdn*mrf) };
    const float s1i[4] = { sigf(xu6.x)*mu,  sigf(xu6.y)*mu, sigf(xu6.z)*mu, sigf(xu6.w)*mu };
    const float s1j[4] = { sigf(xd1.x)*mdn, sigf(xd1.y)*mdn, sigf(xd1.z)*mdn, sigf(xd1.w)*mdn };
    const float s2i[4] = { sigf(xu5.y)*mu,  sigf(xu5.z)*mu, sigf(xu5.w)*mu, sigf(eu5)*(mu*mrf) };
    const float s2j[4] = { sigf(ed2)*(mdn*mlf), sigf(xd2.x)*mdn, sigf(xd2.y)*mdn, sigf(xd2.z)*mdn };
    const float s3i[4] = { sigf(e4l)*mlf,  p[4][0], p[4][1], p[4][2] };
    const float s3j[4] = { p[3][1], p[3][2], p[3][3], sigf(e3r)*mrf };

    // ================= Phase C: votes + BCE products =================
    float pb0[4] = {1.f,1.f,1.f,1.f}, pb1[4] = {1.f,1.f,1.f,1.f};

#define VOTE_PAIR(K, SI, SJ)                                                 \
    _Pragma("unroll")                                                        \
    for (int q = 0; q < 4; q++) {                                            \
        const float vi = p[K][q]     * SI[q];                                \
        const float vj = p[7 - K][q] * SJ[q];                                \
        dacc[q] = fmaxf(dacc[q], fmaxf(sgn[q] * vi, sgn[q] * vj));           \
        const bool bi = (m >> ((K)     + 8 * q)) & 1u;                       \
        const bool bj = (m >> ((7 - K) + 8 * q)) & 1u;                       \
        pb0[q] *= fmaxf(bi ? vi : 1.0f - vi, 1e-7f);                         \
        pb1[q] *= fmaxf(bj ? vj : 1.0f - vj, 1e-7f);                         \
    }

    VOTE_PAIR(0, s0i, s0j)
    VOTE_PAIR(1, s1i, s1j)
    VOTE_PAIR(2, s2i, s2j)
    VOTE_PAIR(3, s3i, s3j)
#undef VOTE_PAIR

    // ================= Phase D: logs + decouple =================
    float acc = 0.0f;
    #pragma unroll
    for (int q = 0; q < 4; q++) {
        const float lbi  = -(__logf(pb0[q]) + __logf(pb1[q]));
        const float lcon = -(__logf(pc0[q]) + __logf(pc1[q]));
        // edge: dacc = -vmin -> d = 1 + dacc ; else d = vmax = dacc
        const float d  = edge[q] ? (1.0f + dacc[q]) : dacc[q];
        const float dc = clipf(d);
        const float tg = (q == 0) ? tg4.x : (q == 1) ? tg4.y : (q == 2) ? tg4.z : tg4.w;
        const float de = -(tg * __logf(dc) + (1.0f - tg) * __logf(1.0f - dc));
        acc += fmaf(0.8f, lcon, fmaf(0.2f, lbi, de));
    }

    // ---- block reduction ----
    #pragma unroll
    for (int o = 16; o > 0; o >>= 1)
        acc += __shfl_xor_sync(0xffffffffu, acc, o);

    __shared__ float  wsf[8];
    __shared__ double wsd[8];
    __shared__ bool   s_last;
    const int lane = threadIdx.x & 31, warp = threadIdx.x >> 5;
    if (lane == 0) wsf[warp] = acc;
    __syncthreads();
    if (warp == 0) {
        float v = (lane < 8) ? wsf[lane] : 0.0f;
        #pragma unroll
        for (int o = 4; o > 0; o >>= 1)
            v += __shfl_xor_sync(0xffffffffu, v, o);
        if (lane == 0) {
            g_part[blockIdx.x] = v;
            __threadfence();
            const unsigned c = atomicAdd(&g_cnt, 1u);
            s_last = (c == (unsigned)(NBLK - 1));
        }
    }
    __syncthreads();

    // ---- last block: deterministic final reduce in double ----
    if (s_last) {
        __threadfence();
        double v = 0.0;
        for (int i = threadIdx.x; i < NBLK; i += TPB)
            v += (double)g_part[i];
        #pragma unroll
        for (int o = 16; o > 0; o >>= 1)
            v += __shfl_xor_sync(0xffffffffu, v, o);
        if (lane == 0) wsd[warp] = v;
        __syncthreads();
        if (warp == 0) {
            double t = (lane < 8) ? wsd[lane] : 0.0;
            #pragma unroll
            for (int o = 4; o > 0; o >>= 1)
                t += __shfl_xor_sync(0xffffffffu, t, o);
            if (lane == 0) {
                out[0] = (float)t;
                __threadfence();
                g_cnt = 0;   // reset for next graph replay
            }
        }
    }
}

extern "C" void kernel_launch(void* const* d_in, const int* in_sizes, int n_in,
                              void* d_out, int out_size)
{
    const float* c_map  = (const float*)d_in[0];
    const float* target = (const float*)d_in[1];
    const int*   con    = (const int*)  d_in[2];
    bicon_loss_kernel<<<NBLK, TPB>>>(c_map, target, con, (float*)d_out);
}

// round 10
// speedup vs baseline: 1.0820x; 1.0820x over previous
#include <cuda_runtime.h>

// bicon_loss fused single kernel, R10:
//  R8 base (4 px/thread, channel pairs, con front-batch, 64-reg/occ-4 point)
//  + branch-free clamped neighbor loads (validity as multiplicative masks)
//    so ptxas can pipeline pair K+1 loads over pair K compute.

#define BB 16
#define HH 352
#define WW 352
#define HW (HH * WW)
#define WV (WW / 4)              // 88 vec-cols
#define NTH (BB * HH * WV)       // 495616 threads
#define TPB 256
#define NBLK (NTH / TPB)         // 1936 exactly

__device__ float        g_part[NBLK];
__device__ unsigned int g_cnt = 0;

__device__ __forceinline__ float sigf(float x) {
    float t;
    asm("tanh.approx.f32 %0, %1;" : "=f"(t) : "f"(x * 0.5f));
    return fmaf(0.5f, t, 0.5f);
}
__device__ __forceinline__ float clipf(float v) {
    return fminf(fmaxf(v, 1e-7f), 1.0f - 1e-7f);
}

// Pair K: i=K shift (DX,DY); j=7-K shift (-DX,-DY).
// vote_i(h,w) = p_i(h,w) * p_j(h-DY, w-DX); vote_j(h,w) = p_j(h,w) * p_i(h+DY, w+DX)
// All loads branch-free: hs_u/hs_d are clamped row offsets, m* are 0/1 masks.
template<int K, int DX>
__device__ __forceinline__ void do_pair_v(
    const float* __restrict__ cmb, unsigned m,
    int hs_u, int hs_d, float mu, float mdn,
    int ol, int orr, float mlf, float mrf,
    const float* sgn, float* dacc,
    float* pb0, float* pb1, float* pc0, float* pc1)
{
    constexpr int CI = K;
    constexpr int CJ = 7 - K;

    // ---- independent loads for this pair (no branches -> early issue) ----
    const float4 xi = *(const float4*)(cmb + CI * HW);
    const float4 xj = *(const float4*)(cmb + CJ * HW);
    const float4 xu = *(const float4*)(cmb + CJ * HW + hs_u);   // row h-1 src
    const float4 xd = *(const float4*)(cmb + CI * HW + hs_d);   // row h+1 src
    float eu = 0.0f, ed = 0.0f;
    if constexpr (DX == 1) {
        eu = (cmb + CJ * HW + hs_u)[ol];    // si q0 (left edge)
        ed = (cmb + CI * HW + hs_d)[orr];   // sj q3 (right edge)
    } else if constexpr (DX == -1) {
        eu = (cmb + CJ * HW + hs_u)[orr];   // si q3 (right edge)
        ed = (cmb + CI * HW + hs_d)[ol];    // sj q0 (left edge)
    }

    const float pi[4] = { sigf(xi.x), sigf(xi.y), sigf(xi.z), sigf(xi.w) };
    const float pj[4] = { sigf(xj.x), sigf(xj.y), sigf(xj.z), sigf(xj.w) };

    float si[4], sj[4];
    if constexpr (DX == 1) {
        si[0] = sigf(eu)   * (mu * mlf);
        si[1] = sigf(xu.x) * mu;  si[2] = sigf(xu.y) * mu;  si[3] = sigf(xu.z) * mu;
        sj[0] = sigf(xd.y) * mdn; sj[1] = sigf(xd.z) * mdn; sj[2] = sigf(xd.w) * mdn;
        sj[3] = sigf(ed)   * (mdn * mrf);
    } else if constexpr (DX == 0) {
        si[0] = sigf(xu.x) * mu;  si[1] = sigf(xu.y) * mu;
        si[2] = sigf(xu.z) * mu;  si[3] = sigf(xu.w) * mu;
        sj[0] = sigf(xd.x) * mdn; sj[1] = sigf(xd.y) * mdn;
        sj[2] = sigf(xd.z) * mdn; sj[3] = sigf(xd.w) * mdn;
    } else {
        si[0] = sigf(xu.y) * mu;  si[1] = sigf(xu.z) * mu;  si[2] = sigf(xu.w) * mu;
        si[3] = sigf(eu)   * (mu * mrf);
        sj[0] = sigf(ed)   * (mdn * mlf);
        sj[1] = sigf(xd.x) * mdn; sj[2] = sigf(xd.y) * mdn; sj[3] = sigf(xd.z) * mdn;
    }

    #pragma unroll
    for (int q = 0; q < 4; q++) {
        const float vi = pi[q] * si[q];
        const float vj = pj[q] * sj[q];
        dacc[q] = fmaxf(dacc[q], fmaxf(sgn[q] * vi, sgn[q] * vj));
        const bool bi = (m >> (CI + 8 * q)) & 1u;
        const bool bj = (m >> (CJ + 8 * q)) & 1u;
        pb0[q] *= fmaxf(bi ? vi    : 1.0f - vi,    1e-7f);
        pb1[q] *= fmaxf(bj ? vj    : 1.0f - vj,    1e-7f);
        pc0[q] *= fmaxf(bi ? pi[q] : 1.0f - pi[q], 1e-7f);
        pc1[q] *= fmaxf(bj ? pj[q] : 1.0f - pj[q], 1e-7f);
    }
}

// Pair 3 (DX=1, DY=0): row-h shifts reuse self sigmoids.
__device__ __forceinline__ void do_pair3(
    const float* __restrict__ cmb, unsigned m,
    int ol, int orr, float mlf, float mrf,
    const float* sgn, float* dacc,
    float* pb0, float* pb1, float* pc0, float* pc1)
{
    const float4 xi = *(const float4*)(cmb + 3 * HW);
    const float4 xj = *(const float4*)(cmb + 4 * HW);
    const float e4l = cmb[4 * HW + ol];
    const float e3r = cmb[3 * HW + orr];

    const float pi[4] = { sigf(xi.x), sigf(xi.y), sigf(xi.z), sigf(xi.w) };
    const float pj[4] = { sigf(xj.x), sigf(xj.y), sigf(xj.z), sigf(xj.w) };

    const float si[4] = { sigf(e4l) * mlf, pj[0], pj[1], pj[2] };   // ch4, w-1
    const float sj[4] = { pi[1], pi[2], pi[3], sigf(e3r) * mrf };   // ch3, w+1

    #pragma unroll
    for (int q = 0; q < 4; q++) {
        const float vi = pi[q] * si[q];
        const float vj = pj[q] * sj[q];
        dacc[q] = fmaxf(dacc[q], fmaxf(sgn[q] * vi, sgn[q] * vj));
        const bool bi = (m >> (3 + 8 * q)) & 1u;
        const bool bj = (m >> (4 + 8 * q)) & 1u;
        pb0[q] *= fmaxf(bi ? vi    : 1.0f - vi,    1e-7f);
        pb1[q] *= fmaxf(bj ? vj    : 1.0f - vj,    1e-7f);
        pc0[q] *= fmaxf(bi ? pi[q] : 1.0f - pi[q], 1e-7f);
        pc1[q] *= fmaxf(bj ? pj[q] : 1.0f - pj[q], 1e-7f);
    }
}

__global__ void __launch_bounds__(TPB, 4)
bicon_loss_kernel(const float* __restrict__ c_map,
                  const float* __restrict__ target,
                  const int*   __restrict__ con,
                  float*       __restrict__ out)
{
    const int tid  = blockIdx.x * TPB + threadIdx.x;   // grid covers NTH exactly
    const int wv   = tid % WV;
    const int rest = tid / WV;
    const int h    = rest % HH;
    const int b    = rest / HH;
    const int w0   = wv * 4;

    const size_t roff = (size_t)h * WW + w0;
    const float* cmb = c_map + (size_t)b * 8 * HW + roff;
    const int*   cnb = con   + (size_t)b * 8 * HW + roff;

    const bool wl = (w0 > 0), wr = (wv < WV - 1);
    const int   hs_u = (h > 0)      ? -WW : 0;
    const int   hs_d = (h < HH - 1) ?  WW : 0;
    const float mu   = (h > 0)      ? 1.0f : 0.0f;
    const float mdn  = (h < HH - 1) ? 1.0f : 0.0f;
    const int   ol   = wl ? -1 : 0;
    const int   orr  = wr ?  4 : 3;
    const float mlf  = wl ? 1.0f : 0.0f;
    const float mrf  = wr ? 1.0f : 0.0f;

    // ---- con front-batch: 8 independent int4 -> one 32-bit mask ----
    unsigned m = 0u;        // bit (c + 8q)
    #pragma unroll
    for (int c = 0; c < 8; c++) {
        const int4 t = __ldcs((const int4*)(cnb + c * HW));
        m |= ((unsigned)(t.x != 0) << (c + 0))
           | ((unsigned)(t.y != 0) << (c + 8))
           | ((unsigned)(t.z != 0) << (c + 16))
           | ((unsigned)(t.w != 0) << (c + 24));
    }
    const float4 tg4 = __ldcs((const float4*)(target + (size_t)b * HW + roff));

    bool  edge[4];
    float sgn[4], dacc[4];
    #pragma unroll
    for (int q = 0; q < 4; q++) {
        const int sc = __popc((m >> (8 * q)) & 0xffu);
        edge[q] = (sc > 0) && (sc < 8);
        sgn[q]  = edge[q] ? -1.0f : 1.0f;
        dacc[q] = -1e30f;
    }

    float pb0[4] = {1.f,1.f,1.f,1.f}, pb1[4] = {1.f,1.f,1.f,1.f};
    float pc0[4] = {1.f,1.f,1.f,1.f}, pc1[4] = {1.f,1.f,1.f,1.f};

    // SHIFTS: k=0:(1,1)  k=1:(0,1)  k=2:(-1,1)  k=3:(1,0)
    do_pair_v<0,  1>(cmb, m, hs_u, hs_d, mu, mdn, ol, orr, mlf, mrf, sgn, dacc, pb0, pb1, pc0, pc1);
    do_pair_v<1,  0>(cmb, m, hs_u, hs_d, mu, mdn, ol, orr, mlf, mrf, sgn, dacc, pb0, pb1, pc0, pc1);
    do_pair_v<2, -1>(cmb, m, hs_u, hs_d, mu, mdn, ol, orr, mlf, mrf, sgn, dacc, pb0, pb1, pc0, pc1);
    do_pair3(cmb, m, ol, orr, mlf, mrf, sgn, dacc, pb0, pb1, pc0, pc1);

    float acc = 0.0f;
    #pragma unroll
    for (int q = 0; q < 4; q++) {
        const float lbi  = -(__logf(pb0[q]) + __logf(pb1[q]));
        const float lcon = -(__logf(pc0[q]) + __logf(pc1[q]));
        const float d  = edge[q] ? (1.0f + dacc[q]) : dacc[q];   // 1-vmin / vmax
        const float dc = clipf(d);
        const float tg = (q == 0) ? tg4.x : (q == 1) ? tg4.y : (q == 2) ? tg4.z : tg4.w;
        const float de = -(tg * __logf(dc) + (1.0f - tg) * __logf(1.0f - dc));
        acc += fmaf(0.8f, lcon, fmaf(0.2f, lbi, de));
    }

    // ---- block reduction ----
    #pragma unroll
    for (int o = 16; o > 0; o >>= 1)
        acc += __shfl_xor_sync(0xffffffffu, acc, o);

    __shared__ float  wsf[8];
    __shared__ double wsd[8];
    __shared__ bool   s_last;
    const int lane = threadIdx.x & 31, warp = threadIdx.x >> 5;
    if (lane == 0) wsf[warp] = acc;
    __syncthreads();
    if (warp == 0) {
        float v = (lane < 8) ? wsf[lane] : 0.0f;
        #pragma unroll
        for (int o = 4; o > 0; o >>= 1)
            v += __shfl_xor_sync(0xffffffffu, v, o);
        if (lane == 0) {
            g_part[blockIdx.x] = v;
            __threadfence();
            const unsigned c = atomicAdd(&g_cnt, 1u);
            s_last = (c == (unsigned)(NBLK - 1));
        }
    }
    __syncthreads();

    // ---- last block: deterministic final reduce in double ----
    if (s_last) {
        __threadfence();
        double v = 0.0;
        for (int i = threadIdx.x; i < NBLK; i += TPB)
            v += (double)g_part[i];
        #pragma unroll
        for (int o = 16; o > 0; o >>= 1)
            v += __shfl_xor_sync(0xffffffffu, v, o);
        if (lane == 0) wsd[warp] = v;
        __syncthreads();
        if (warp == 0) {
            double t = (lane < 8) ? wsd[lane] : 0.0;
            #pragma unroll
            for (int o = 4; o > 0; o >>= 1)
                t += __shfl_xor_sync(0xffffffffu, t, o);
            if (lane == 0) {
                out[0] = (float)t;
                __threadfence();
                g_cnt = 0;   // reset for next graph replay
            }
        }
    }
}

extern "C" void kernel_launch(void* const* d_in, const int* in_sizes, int n_in,
                              void* d_out, int out_size)
{
    const float* c_map  = (const float*)d_in[0];
    const float* target = (const float*)d_in[1];
    const int*   con    = (const int*)  d_in[2];
    bicon_loss_kernel<<<NBLK, TPB>>>(c_map, target, con, (float*)d_out);
}